// round 13
// baseline (speedup 1.0000x reference)
#include <cuda_runtime.h>
#include <math.h>
#include <stdint.h>

#define BB 4
#define NN 20000
#define EE 100000
#define CC 128
#define NM 32

// ---------------- scratch (static device globals; no allocation) -------------
__device__ float d_hA[BB * NN * CC];
__device__ float d_hB[BB * NN * CC];
__device__ float d_g[(size_t)BB * NN * 384];
__device__ float d_cosv[BB * NN * NM];
__device__ float d_sinv[BB * NN * NM];
__device__ float d_xcs3[(size_t)3 * BB * 65 * CC];
__device__ float d_specW[BB * 64 * CC];
__device__ float d_f0[BB * CC];
__device__ float d_wcat3[3 * 512 * CC];
__device__ float d_wtc3[3 * NM * CC * CC];
__device__ float d_wts3[3 * NM * CC * CC];
__device__ float d_fc1wt[CC * CC];
// CSR scratch
__device__ int   d_count[BB * NN];
__device__ int   d_cursor[BB * NN];
__device__ int   d_offsets[BB * (NN + 1)];
__device__ int   d_esrc[BB * EE];
__device__ float d_ew3[(size_t)BB * EE * 3];

__device__ __forceinline__ float gelu_f(float v) {
    return 0.5f * v * (1.f + erff(v * 0.70710678118654752f));
}

__device__ __forceinline__ float to_tf32(float x) {
    uint32_t u;
    asm("cvt.rna.tf32.f32 %0, %1;" : "=r"(u) : "f"(x));
    return __uint_as_float(u);
}

__device__ __forceinline__ void mma_tf32(float* d, const uint32_t* a, const uint32_t* b) {
    asm volatile(
        "mma.sync.aligned.m16n8k8.row.col.f32.tf32.tf32.f32 "
        "{%0,%1,%2,%3}, {%4,%5,%6,%7}, {%8,%9}, {%0,%1,%2,%3};"
        : "+f"(d[0]), "+f"(d[1]), "+f"(d[2]), "+f"(d[3])
        : "r"(a[0]), "r"(a[1]), "r"(a[2]), "r"(a[3]), "r"(b[0]), "r"(b[1]));
}

__device__ __forceinline__ void cp16(void* smem_dst, const void* gsrc, int src_bytes) {
    uint32_t d = (uint32_t)__cvta_generic_to_shared(smem_dst);
    asm volatile("cp.async.cg.shared.global [%0], [%1], 16, %2;"
                 :: "r"(d), "l"(gsrc), "r"(src_bytes));
}
#define CP_COMMIT asm volatile("cp.async.commit_group;")
#define CP_WAIT(n) asm volatile("cp.async.wait_group %0;" :: "n"(n))

// ---------------- basis ------------------------------------------------------
__global__ void basis_kernel(const float* __restrict__ nodes,
                             const float* __restrict__ modes,
                             const float* __restrict__ latent,
                             float* __restrict__ cosv, float* __restrict__ sinv) {
    int idx = blockIdx.x * blockDim.x + threadIdx.x;
    if (idx >= BB * NN) return;
    float il0 = 0.5f + 1.5f / (1.f + expf(-latent[0]));
    float il1 = 0.5f + 1.5f / (1.f + expf(-latent[1]));
    float il2 = 0.5f + 1.5f / (1.f + expf(-latent[2]));
    float n0 = nodes[idx * 3 + 0];
    float n1 = nodes[idx * 3 + 1];
    float n2 = nodes[idx * 3 + 2];
    #pragma unroll
    for (int k = 0; k < NM; k++) {
        float t = n0 * modes[k * 3 + 0] * il0
                + n1 * modes[k * 3 + 1] * il1
                + n2 * modes[k * 3 + 2] * il2;
        float s, c;
        sincosf(t, &s, &c);
        cosv[idx * NM + k] = to_tf32(c);
        sinv[idx * NM + k] = to_tf32(s);
    }
}

// ---------------- fc0 --------------------------------------------------------
__global__ void fc0_kernel(const float* __restrict__ x, const float* __restrict__ w,
                           const float* __restrict__ bias, float* __restrict__ h) {
    int idx = blockIdx.x * blockDim.x + threadIdx.x;
    if (idx >= BB * NN * CC) return;
    int c = idx & 127;
    int node = idx >> 7;
    float v = bias[c] + x[node * 3 + 0] * w[c * 3 + 0]
                      + x[node * 3 + 1] * w[c * 3 + 1]
                      + x[node * 3 + 2] * w[c * 3 + 2];
    h[idx] = to_tf32(v);
}

// ---------------- CSR build --------------------------------------------------
__global__ void hist_kernel(const int* __restrict__ edges, int* __restrict__ count) {
    int idx = blockIdx.x * blockDim.x + threadIdx.x;
    if (idx >= BB * EE) return;
    int b = idx / EE;
    int tgt = edges[idx * 2 + 0];
    atomicAdd(&count[b * NN + tgt], 1);
}

__global__ void scan_kernel(const int* __restrict__ count, int* __restrict__ offsets) {
    int b = blockIdx.x;
    int t = threadIdx.x;              // 1024
    __shared__ int sums[1024];
    const int CH = 20;
    int base = t * CH;
    int s = 0;
    for (int i = 0; i < CH; i++) {
        int n = base + i;
        if (n < NN) s += count[b * NN + n];
    }
    sums[t] = s;
    __syncthreads();
    for (int off = 1; off < 1024; off <<= 1) {
        int v = (t >= off) ? sums[t - off] : 0;
        __syncthreads();
        sums[t] += v;
        __syncthreads();
    }
    int run = (t == 0) ? 0 : sums[t - 1];
    for (int i = 0; i < CH; i++) {
        int n = base + i;
        if (n < NN) {
            offsets[b * (NN + 1) + n] = run;
            run += count[b * NN + n];
        }
    }
    if (t == 1023) offsets[b * (NN + 1) + NN] = sums[1023];
}

__global__ void fill_kernel(const int* __restrict__ edges, const float* __restrict__ egw,
                            const int* __restrict__ offsets, int* __restrict__ cursor,
                            int* __restrict__ esrc, float* __restrict__ ew3) {
    int idx = blockIdx.x * blockDim.x + threadIdx.x;
    if (idx >= BB * EE) return;
    int b = idx / EE;
    int tgt = edges[idx * 2 + 0];
    int src = edges[idx * 2 + 1];
    int pos = offsets[b * (NN + 1) + tgt] + atomicAdd(&cursor[b * NN + tgt], 1);
    int gp = b * EE + pos;
    esrc[gp] = src;
    ew3[(size_t)gp * 3 + 0] = egw[(size_t)idx * 3 + 0];
    ew3[(size_t)gp * 3 + 1] = egw[(size_t)idx * 3 + 1];
    ew3[(size_t)gp * 3 + 2] = egw[(size_t)idx * 3 + 2];
}

// ---------------- gradient gather (per-batch) --------------------------------
#define NPB 8
#define ECH 128
__global__ void __launch_bounds__(128)
gather_kernel(const float* __restrict__ h,
              const int* __restrict__ offsets,
              const int* __restrict__ esrc,
              const float* __restrict__ ew3,
              float* __restrict__ g) {
    int c = threadIdx.x;   // 128
    int n0 = blockIdx.x * NPB;
    __shared__ int s_off[NPB + 1];
    __shared__ int s_src[ECH];
    __shared__ float s_w[ECH * 3];
    if (c <= NPB) s_off[c] = offsets[n0 + c];
    __syncthreads();
    int e0 = s_off[0], e1 = s_off[NPB];
    float ht[NPB];
    float acc[NPB][3];
    #pragma unroll
    for (int i = 0; i < NPB; i++) {
        ht[i] = h[(n0 + i) * CC + c];
        acc[i][0] = acc[i][1] = acc[i][2] = 0.f;
    }
    for (int cbase = e0; cbase < e1; cbase += ECH) {
        int cnt = min(ECH, e1 - cbase);
        __syncthreads();
        if (c < cnt) s_src[c] = esrc[cbase + c];
        for (int l = c; l < cnt * 3; l += 128)
            s_w[l] = ew3[(size_t)cbase * 3 + l];
        __syncthreads();
        #pragma unroll
        for (int i = 0; i < NPB; i++) {
            int lo = max(s_off[i] - cbase, 0);
            int hi = min(s_off[i + 1] - cbase, cnt);
            for (int j = lo; j < hi; j++) {
                float hs = h[s_src[j] * CC + c];
                float d = hs - ht[i];
                acc[i][0] += s_w[j * 3 + 0] * d;
                acc[i][1] += s_w[j * 3 + 1] * d;
                acc[i][2] += s_w[j * 3 + 2] * d;
            }
        }
    }
    #pragma unroll
    for (int i = 0; i < NPB; i++) {
        size_t gb_ = (size_t)(n0 + i) * 384 + c * 3;
        g[gb_ + 0] = to_tf32(acc[i][0]);
        g[gb_ + 1] = to_tf32(acc[i][1]);
        g[gb_ + 2] = to_tf32(acc[i][2]);
    }
}

// ---------------- forward spectral transform (per-batch) ---------------------
#define FNCH 200
__global__ void __launch_bounds__(256)
forward_mma(const float* __restrict__ h,
            const float* __restrict__ cosv,
            const float* __restrict__ sinv,
            const float* __restrict__ nw,
            float* __restrict__ xcs) {
    __shared__ float Ah[80][20];
    __shared__ float Hs[2][16][136];
    int n0 = blockIdx.x * FNCH;
    int tid = threadIdx.x;
    int warp = tid >> 5, lane = tid & 31;
    int grp = lane >> 2, tig = lane & 3;

    float acc[5][2][4];
    #pragma unroll
    for (int m = 0; m < 5; m++)
        #pragma unroll
        for (int f = 0; f < 2; f++)
            #pragma unroll
            for (int q = 0; q < 4; q++) acc[m][f][q] = 0.f;

    auto issue_h = [&](int kt, int buf) {
        int base_node = n0 + kt * 16;
        #pragma unroll
        for (int r = 0; r < 2; r++) {
            int gi = tid + r * 256;
            int row = gi >> 5;
            int c4 = (gi & 31) * 4;
            cp16(&Hs[buf][row][c4], h + (size_t)(base_node + row) * CC + c4, 16);
        }
    };

    issue_h(0, 0); CP_COMMIT;

    const int CHUNKS = (FNCH + 15) / 16;
    for (int kt = 0; kt < CHUNKS; kt++) {
        int cur = kt & 1;
        int base_node = n0 + kt * 16;
        int valid = min(16, FNCH - kt * 16);
        #pragma unroll
        for (int i = 0; i < 5; i++) {
            int idx = tid + i * 256;
            int j = idx / 80;
            int r = idx - j * 80;
            float v = 0.f;
            if (j < valid) {
                int node = base_node + j;
                float w = nw[node];
                if (r < 32)       v = w * cosv[(size_t)node * NM + r];
                else if (r < 64)  v = w * sinv[(size_t)node * NM + (r - 32)];
                else if (r == 64) v = w;
            }
            Ah[r][j] = to_tf32(v);
        }
        if (kt < CHUNKS - 1) { issue_h(kt + 1, cur ^ 1); CP_COMMIT; CP_WAIT(1); }
        else                 { CP_WAIT(0); }
        __syncthreads();

        #pragma unroll
        for (int k8 = 0; k8 < 2; k8++) {
            int k0 = k8 * 8;
            uint32_t bfr[2][2];
            #pragma unroll
            for (int f = 0; f < 2; f++) {
                int ncol = warp * 16 + f * 8 + grp;
                bfr[f][0] = __float_as_uint(Hs[cur][k0 + tig][ncol]);
                bfr[f][1] = __float_as_uint(Hs[cur][k0 + tig + 4][ncol]);
            }
            uint32_t afr[5][4];
            #pragma unroll
            for (int m = 0; m < 5; m++) {
                int r0 = m * 16 + grp;
                afr[m][0] = __float_as_uint(Ah[r0][k0 + tig]);
                afr[m][1] = __float_as_uint(Ah[r0 + 8][k0 + tig]);
                afr[m][2] = __float_as_uint(Ah[r0][k0 + tig + 4]);
                afr[m][3] = __float_as_uint(Ah[r0 + 8][k0 + tig + 4]);
            }
            #pragma unroll
            for (int m = 0; m < 5; m++)
                #pragma unroll
                for (int f = 0; f < 2; f++)
                    mma_tf32(acc[m][f], afr[m], bfr[f]);
        }
        __syncthreads();
    }

    #pragma unroll
    for (int m = 0; m < 5; m++) {
        #pragma unroll
        for (int f = 0; f < 2; f++) {
            #pragma unroll
            for (int half = 0; half < 2; half++) {
                int row = m * 16 + grp + half * 8;
                if (row < 65) {
                    int col = warp * 16 + f * 8 + tig * 2;
                    atomicAdd(&xcs[(size_t)row * CC + col],     acc[m][f][half * 2 + 0]);
                    atomicAdd(&xcs[(size_t)row * CC + col + 1], acc[m][f][half * 2 + 1]);
                }
            }
        }
    }
}

// ---------------- generic tiled transpose ------------------------------------
__global__ void transpose_kernel(const float* __restrict__ src, float* __restrict__ dst,
                                 int R, int C, int do_round) {
    __shared__ float tile[32][33];
    int c0 = blockIdx.x * 32;
    int r0 = blockIdx.y * 32;
    int tx = threadIdx.x, ty = threadIdx.y;
    #pragma unroll
    for (int i = 0; i < 4; i++) {
        int r = r0 + ty + i * 8;
        int c = c0 + tx;
        if (r < R && c < C) tile[ty + i * 8][tx] = src[r * C + c];
    }
    __syncthreads();
    #pragma unroll
    for (int i = 0; i < 4; i++) {
        int c = c0 + ty + i * 8;
        int r = r0 + tx;
        if (r < R && c < C) {
            float v = tile[tx][ty + i * 8];
            dst[c * R + r] = do_round ? to_tf32(v) : v;
        }
    }
}

// ---------------- mode mixing (per-batch, grid (1,33)) -----------------------
__global__ void modemix_kernel(const float* __restrict__ xcs,
                               const float* __restrict__ wtc,
                               const float* __restrict__ wts,
                               const float* __restrict__ sw0_l,
                               float* __restrict__ specW, float* __restrict__ f0) {
    int k = blockIdx.y;
    int o = threadIdx.x;
    __shared__ float xc_s[CC], xs_s[CC];
    if (k < 32) {
        xc_s[o] = xcs[k * CC + o];
        xs_s[o] = xcs[(32 + k) * CC + o];
        __syncthreads();
        float fc = 0.f, fs = 0.f;
        #pragma unroll 8
        for (int c = 0; c < CC; c++) {
            float wc = wtc[(k * CC + c) * CC + o];
            float ws = wts[(k * CC + c) * CC + o];
            float a = xc_s[c], s2 = xs_s[c];
            fc += a * wc - s2 * ws;
            fs += s2 * wc + a * ws;
        }
        specW[k * CC + o]        = to_tf32( 2.f * fc);
        specW[(32 + k) * CC + o] = to_tf32(-2.f * fs);
    } else {
        xc_s[o] = xcs[64 * CC + o];
        __syncthreads();
        float f = 0.f;
        #pragma unroll 8
        for (int c = 0; c < CC; c++) f += xc_s[c] * sw0_l[c * CC + o];
        f0[o] = f;
    }
}

// ---------------- fused combine GEMM (per-batch) -----------------------------
#define CSTAGES 4
#define A_EL (64 * 36)
#define W_EL (16 * 136)
#define CSMEM_BYTES ((CSTAGES * (A_EL + W_EL) + 128) * 4)
__global__ void __launch_bounds__(128, 3)
combine_mma(const float* __restrict__ h, const float* __restrict__ g,
            const float* __restrict__ cosv, const float* __restrict__ sinv,
            const float* __restrict__ wcat, const float* __restrict__ specW,
            const float* __restrict__ f0, const float* __restrict__ wb,
            const float* __restrict__ gb, float* __restrict__ hout,
            int gelu_flag) {
    extern __shared__ float dsm[];
    float (*As)[64][36] = (float(*)[64][36])dsm;
    float (*Ws)[16][136] = (float(*)[16][136])(dsm + CSTAGES * A_EL);
    float* bias_s = dsm + CSTAGES * (A_EL + W_EL);

    int n0 = blockIdx.x * 64;
    int tid = threadIdx.x;          // 128
    int warp = tid >> 5, lane = tid & 31;
    int grp = lane >> 2, tig = lane & 3;
    int wm = (warp >> 1) * 32;
    int wn = (warp & 1) * 64;

    bias_s[tid] = wb[tid] + gb[tid] + f0[tid];

    float acc[2][8][4];
    #pragma unroll
    for (int i = 0; i < 2; i++)
        #pragma unroll
        for (int j = 0; j < 8; j++)
            #pragma unroll
            for (int q = 0; q < 4; q++) acc[i][j][q] = 0.f;

    auto issue_tile = [&](int kt, int buf) {
        int kbase = kt * 16;
        #pragma unroll
        for (int r = 0; r < 2; r++) {
            int gi = tid + r * 128;
            int m = gi >> 2;
            int k4 = (gi & 3) * 4;
            int n = n0 + m;
            int nc = (n < NN) ? n : 0;
            int k = kbase + k4;
            const float* src;
            if (k < 128)      src = h + (size_t)nc * 128 + k;
            else if (k < 512) src = g + (size_t)nc * 384 + (k - 128);
            else if (k < 544) src = cosv + (size_t)nc * 32 + (k - 512);
            else              src = sinv + (size_t)nc * 32 + (k - 544);
            cp16(&As[buf][m][k4], src, (n < NN) ? 16 : 0);
        }
        #pragma unroll
        for (int r = 0; r < 4; r++) {
            int gi = tid + r * 128;
            int kk = gi >> 5;
            int o4 = (gi & 31) * 4;
            int k = kbase + kk;
            const float* src = (k < 512) ? wcat + (size_t)k * 128 + o4
                                         : specW + (size_t)(k - 512) * 128 + o4;
            cp16(&Ws[buf][kk][o4], src, 16);
        }
    };

    issue_tile(0, 0); CP_COMMIT;
    issue_tile(1, 1); CP_COMMIT;
    issue_tile(2, 2); CP_COMMIT;

    for (int kt = 0; kt < 36; kt++) {
        int cur = kt & 3;
        if (kt <= 33) CP_WAIT(2);
        else if (kt == 34) CP_WAIT(1);
        else CP_WAIT(0);
        __syncthreads();
        if (kt < 33) {
            issue_tile(kt + 3, (kt + 3) & 3);
            CP_COMMIT;
        }
        #pragma unroll
        for (int k8 = 0; k8 < 2; k8++) {
            int k0 = k8 * 8;
            uint32_t afr[2][4];
            #pragma unroll
            for (int i = 0; i < 2; i++) {
                int r0 = wm + i * 16 + grp;
                afr[i][0] = __float_as_uint(As[cur][r0][k0 + tig]);
                afr[i][1] = __float_as_uint(As[cur][r0 + 8][k0 + tig]);
                afr[i][2] = __float_as_uint(As[cur][r0][k0 + tig + 4]);
                afr[i][3] = __float_as_uint(As[cur][r0 + 8][k0 + tig + 4]);
            }
            uint32_t bfr[8][2];
            #pragma unroll
            for (int j = 0; j < 8; j++) {
                int o = wn + j * 8 + grp;
                bfr[j][0] = __float_as_uint(Ws[cur][k0 + tig][o]);
                bfr[j][1] = __float_as_uint(Ws[cur][k0 + tig + 4][o]);
            }
            #pragma unroll
            for (int i = 0; i < 2; i++)
                #pragma unroll
                for (int j = 0; j < 8; j++)
                    mma_tf32(acc[i][j], afr[i], bfr[j]);
        }
    }

    // epilogue
    #pragma unroll
    for (int i = 0; i < 2; i++) {
        int row0 = wm + i * 16 + grp;
        #pragma unroll
        for (int j = 0; j < 8; j++) {
            int col = wn + j * 8 + tig * 2;
            #pragma unroll
            for (int half = 0; half < 2; half++) {
                int n = n0 + row0 + half * 8;
                if (n < NN) {
                    float v0 = acc[i][j][half * 2 + 0] + bias_s[col];
                    float v1 = acc[i][j][half * 2 + 1] + bias_s[col + 1];
                    if (gelu_flag) {
                        v0 = to_tf32(gelu_f(v0));
                        v1 = to_tf32(gelu_f(v1));
                    }
                    hout[(size_t)n * CC + col]     = v0;
                    hout[(size_t)n * CC + col + 1] = v1;
                }
            }
        }
    }
}

// ---------------- final fused MLP GEMM ---------------------------------------
__global__ void __launch_bounds__(256, 2)
final_gemm(const float* __restrict__ h, const float* __restrict__ fc1wt,
           const float* __restrict__ fc1_b, const float* __restrict__ fc2_w,
           const float* __restrict__ fc2_b, float* __restrict__ out) {
    int m0 = blockIdx.x * 128;
    int tid = threadIdx.x;
    int tx = tid & 15, ty = tid >> 4;
    __shared__ float As[128][17];
    __shared__ float Ws[16][128];
    float acc[8][8];
    #pragma unroll
    for (int i = 0; i < 8; i++)
        #pragma unroll
        for (int j = 0; j < 8; j++) acc[i][j] = 0.f;

    for (int kt = 0; kt < 8; kt++) {
        int kbase = kt * 16;
        #pragma unroll
        for (int r = 0; r < 8; r++) {
            int l = tid + r * 256;
            int nl = l >> 4, kk = l & 15;
            As[nl][kk] = h[(m0 + nl) * CC + kbase + kk];
        }
        #pragma unroll
        for (int r = 0; r < 8; r++) {
            int l = tid + r * 256;
            int kk = l >> 7, o = l & 127;
            Ws[kk][o] = fc1wt[(kbase + kk) * CC + o];
        }
        __syncthreads();
        #pragma unroll
        for (int kk = 0; kk < 16; kk++) {
            float a[8];
            #pragma unroll
            for (int i = 0; i < 8; i++) a[i] = As[ty + 16 * i][kk];
            float4 w0 = *(const float4*)&Ws[kk][tx * 4];
            float4 w1 = *(const float4*)&Ws[kk][64 + tx * 4];
            float w[8] = {w0.x, w0.y, w0.z, w0.w, w1.x, w1.y, w1.z, w1.w};
            #pragma unroll
            for (int i = 0; i < 8; i++)
                #pragma unroll
                for (int j = 0; j < 8; j++) acc[i][j] += a[i] * w[j];
        }
        __syncthreads();
    }
    float part[8];
    #pragma unroll
    for (int i = 0; i < 8; i++) {
        float p = 0.f;
        #pragma unroll
        for (int j = 0; j < 8; j++) {
            int o = (j < 4) ? (tx * 4 + j) : (64 + tx * 4 + (j - 4));
            float v = acc[i][j] + fc1_b[o];
            v = gelu_f(v);
            p += v * fc2_w[o];
        }
        part[i] = p;
    }
    __syncthreads();
    #pragma unroll
    for (int i = 0; i < 8; i++) As[ty + 16 * i][tx] = part[i];
    __syncthreads();
    if (tid < 128) {
        float s = 0.f;
        #pragma unroll
        for (int t = 0; t < 16; t++) s += As[tid][t];
        out[m0 + tid] = s + fc2_b[0];
    }
}

// ---------------- launcher ----------------------------------------------------
extern "C" void kernel_launch(void* const* d_in, const int* in_sizes, int n_in,
                              void* d_out, int out_size) {
    const float* x      = (const float*)d_in[0];
    const float* nodes  = (const float*)d_in[2];
    const float* nw     = (const float*)d_in[3];
    const int*   edges  = (const int*)  d_in[4];
    const float* egw    = (const float*)d_in[5];
    const float* modes  = (const float*)d_in[6];
    const float* latent = (const float*)d_in[7];
    const float* fc0_w  = (const float*)d_in[8];
    const float* fc0_b  = (const float*)d_in[9];
    const float* swc    = (const float*)d_in[10];
    const float* sws    = (const float*)d_in[11];
    const float* sw0    = (const float*)d_in[12];
    const float* ww     = (const float*)d_in[13];
    const float* wb     = (const float*)d_in[14];
    const float* gw     = (const float*)d_in[15];
    const float* gb     = (const float*)d_in[16];
    const float* fc1_w  = (const float*)d_in[17];
    const float* fc1_b  = (const float*)d_in[18];
    const float* fc2_w  = (const float*)d_in[19];
    const float* fc2_b  = (const float*)d_in[20];
    float* out = (float*)d_out;

    float *hA, *hB, *g, *cosv, *sinv, *xcs3, *specW, *f0, *wcat3, *wtc3, *wts3, *fc1wt, *ew3;
    int *count, *cursor, *offsets, *esrc;
    cudaGetSymbolAddress((void**)&hA,      d_hA);
    cudaGetSymbolAddress((void**)&hB,      d_hB);
    cudaGetSymbolAddress((void**)&g,       d_g);
    cudaGetSymbolAddress((void**)&cosv,    d_cosv);
    cudaGetSymbolAddress((void**)&sinv,    d_sinv);
    cudaGetSymbolAddress((void**)&xcs3,    d_xcs3);
    cudaGetSymbolAddress((void**)&specW,   d_specW);
    cudaGetSymbolAddress((void**)&f0,      d_f0);
    cudaGetSymbolAddress((void**)&wcat3,   d_wcat3);
    cudaGetSymbolAddress((void**)&wtc3,    d_wtc3);
    cudaGetSymbolAddress((void**)&wts3,    d_wts3);
    cudaGetSymbolAddress((void**)&fc1wt,   d_fc1wt);
    cudaGetSymbolAddress((void**)&count,   d_count);
    cudaGetSymbolAddress((void**)&cursor,  d_cursor);
    cudaGetSymbolAddress((void**)&offsets, d_offsets);
    cudaGetSymbolAddress((void**)&esrc,    d_esrc);
    cudaGetSymbolAddress((void**)&ew3,     d_ew3);

    // ONLY the 2 extra streams proven not to allocate device memory (R7-R11).
    static cudaStream_t s1 = nullptr, s2 = nullptr;
    static cudaEvent_t  ev[12];
    if (s1 == nullptr) {
        cudaStreamCreateWithFlags(&s1, cudaStreamNonBlocking);
        cudaStreamCreateWithFlags(&s2, cudaStreamNonBlocking);
        for (int i = 0; i < 12; i++)
            cudaEventCreateWithFlags(&ev[i], cudaEventDisableTiming);
    }
    enum { E_ROOT = 0, E_FC0, E_BASIS, E_FILL, E_XCS, E_WT0, E_WT1, E_WT2,
           E_BD1, E_BD2 };

    static bool smem_set = false;
    if (!smem_set) {
        cudaFuncSetAttribute(combine_mma, cudaFuncAttributeMaxDynamicSharedMemorySize,
                             CSMEM_BYTES);
        smem_set = true;
    }

    dim3 t32x8(32, 8);
    const size_t XCS_SZ = (size_t)BB * 65 * CC;

    // ---- fork
    cudaEventRecord(ev[E_ROOT], 0);
    cudaStreamWaitEvent(s1, ev[E_ROOT], 0);
    cudaStreamWaitEvent(s2, ev[E_ROOT], 0);

    // S0: fc0 (all batches)
    fc0_kernel<<<(BB * NN * CC + 255) / 256, 256>>>(x, fc0_w, fc0_b, hA);
    cudaEventRecord(ev[E_FC0], 0);

    // S1: basis + CSR
    basis_kernel<<<(BB * NN + 127) / 128, 128, 0, s1>>>(nodes, modes, latent, cosv, sinv);
    cudaEventRecord(ev[E_BASIS], s1);
    cudaMemsetAsync(count, 0, BB * NN * sizeof(int), s1);
    cudaMemsetAsync(cursor, 0, BB * NN * sizeof(int), s1);
    hist_kernel<<<(BB * EE + 255) / 256, 256, 0, s1>>>(edges, count);
    scan_kernel<<<BB, 1024, 0, s1>>>(count, offsets);
    fill_kernel<<<(BB * EE + 255) / 256, 256, 0, s1>>>(edges, egw, offsets, cursor,
                                                       esrc, ew3);
    cudaEventRecord(ev[E_FILL], s1);

    // S2: xcs zero + weight transposes
    cudaMemsetAsync(xcs3, 0, 3 * XCS_SZ * sizeof(float), s2);
    cudaEventRecord(ev[E_XCS], s2);
    transpose_kernel<<<dim3(4, 4), t32x8, 0, s2>>>(fc1_w, fc1wt, CC, CC, 0);
    for (int l = 0; l < 3; l++) {
        transpose_kernel<<<dim3(1, 512), t32x8, 0, s2>>>(
            swc + (size_t)l * CC * CC * NM, wtc3 + (size_t)l * NM * CC * CC, CC * CC, NM, 0);
        transpose_kernel<<<dim3(1, 512), t32x8, 0, s2>>>(
            sws + (size_t)l * CC * CC * NM, wts3 + (size_t)l * NM * CC * CC, CC * CC, NM, 0);
        transpose_kernel<<<dim3(4, 4), t32x8, 0, s2>>>(
            ww + (size_t)l * CC * CC, wcat3 + (size_t)l * 512 * CC, CC, CC, 1);
        transpose_kernel<<<dim3(12, 4), t32x8, 0, s2>>>(
            gw + (size_t)l * CC * 384, wcat3 + (size_t)l * 512 * CC + 128 * CC, CC, 384, 1);
        cudaEventRecord(ev[E_WT0 + l], s2);
    }

    // per-batch chains on streams {0, s1, s2, 0}
    cudaStream_t bmap[BB] = {(cudaStream_t)0, s1, s2, (cudaStream_t)0};
    for (int b = 0; b < BB; b++) {
        cudaStream_t s = bmap[b];
        // cross-stream prerequisites (same-stream waits are no-ops)
        cudaStreamWaitEvent(s, ev[E_FC0], 0);
        cudaStreamWaitEvent(s, ev[E_BASIS], 0);
        cudaStreamWaitEvent(s, ev[E_FILL], 0);
        cudaStreamWaitEvent(s, ev[E_XCS], 0);

        float* hin  = hA + (size_t)b * NN * CC;
        float* hout = hB + (size_t)b * NN * CC;
        float* g_b    = g + (size_t)b * NN * 384;
        const float* cosv_b = cosv + (size_t)b * NN * NM;
        const float* sinv_b = sinv + (size_t)b * NN * NM;
        const float* nw_b   = nw + (size_t)b * NN;
        const int* off_b    = offsets + b * (NN + 1);
        const int* esrc_b   = esrc + (size_t)b * EE;
        const float* ew3_b  = ew3 + (size_t)b * EE * 3;
        float* specW_b = specW + (size_t)b * 64 * CC;
        float* f0_b    = f0 + (size_t)b * CC;

        gather_kernel<<<NN / NPB, 128, 0, s>>>(hin, off_b, esrc_b, ew3_b, g_b);

        for (int l = 0; l < 3; l++) {
            float* xcs_b = xcs3 + (size_t)l * XCS_SZ + (size_t)b * 65 * CC;
            forward_mma<<<NN / FNCH, 256, 0, s>>>(hin, cosv_b, sinv_b, nw_b, xcs_b);
            cudaStreamWaitEvent(s, ev[E_WT0 + l], 0);
            modemix_kernel<<<dim3(1, 33), 128, 0, s>>>(
                xcs_b, wtc3 + (size_t)l * NM * CC * CC, wts3 + (size_t)l * NM * CC * CC,
                sw0 + (size_t)l * CC * CC, specW_b, f0_b);
            combine_mma<<<(NN + 63) / 64, 128, CSMEM_BYTES, s>>>(
                hin, g_b, cosv_b, sinv_b, wcat3 + (size_t)l * 512 * CC, specW_b, f0_b,
                wb + l * CC, gb + l * CC, hout, (l < 2) ? 1 : 0);
            if (l < 2)
                gather_kernel<<<NN / NPB, 128, 0, s>>>(hout, off_b, esrc_b, ew3_b, g_b);
            float* t = hin; hin = hout; hout = t;
        }
        if (b == 1) cudaEventRecord(ev[E_BD1], s);
        if (b == 2) cudaEventRecord(ev[E_BD2], s);
    }

    // join (batches 0 and 3 are stream-0 ordered already) + final
    cudaStreamWaitEvent(0, ev[E_BD1], 0);
    cudaStreamWaitEvent(0, ev[E_BD2], 0);
    final_gemm<<<(BB * NN) / 128, 256>>>(hB, fc1wt, fc1_b, fc2_w, fc2_b, out);
}

// round 14
// speedup vs baseline: 1.3054x; 1.3054x over previous
#include <cuda_runtime.h>
#include <math.h>
#include <stdint.h>

#define BB 4
#define NN 20000
#define EE 100000
#define CC 128
#define NM 32

// ---------------- scratch (static device globals; no allocation) -------------
__device__ float d_hA[BB * NN * CC];
__device__ float d_hB[BB * NN * CC];
__device__ float d_g[(size_t)BB * NN * 384];
__device__ float d_cosv[BB * NN * NM];
__device__ float d_sinv[BB * NN * NM];
__device__ float d_xcs3[(size_t)3 * BB * 65 * CC];
__device__ float d_specW[BB * 64 * CC];
__device__ float d_f0[BB * CC];
__device__ float d_wcat3[3 * 512 * CC];
__device__ float d_wtc3[3 * NM * CC * CC];
__device__ float d_wts3[3 * NM * CC * CC];
__device__ float d_fc1wt[CC * CC];
// CSR scratch
__device__ int   d_count[BB * NN];
__device__ int   d_cursor[BB * NN];
__device__ int   d_offsets[BB * (NN + 1)];
__device__ int   d_esrc[BB * EE];
__device__ float d_ew3[(size_t)BB * EE * 3];

__device__ __forceinline__ float gelu_f(float v) {
    return 0.5f * v * (1.f + erff(v * 0.70710678118654752f));
}

__device__ __forceinline__ float to_tf32(float x) {
    uint32_t u;
    asm("cvt.rna.tf32.f32 %0, %1;" : "=r"(u) : "f"(x));
    return __uint_as_float(u);
}

__device__ __forceinline__ void mma_tf32(float* d, const uint32_t* a, const uint32_t* b) {
    asm volatile(
        "mma.sync.aligned.m16n8k8.row.col.f32.tf32.tf32.f32 "
        "{%0,%1,%2,%3}, {%4,%5,%6,%7}, {%8,%9}, {%0,%1,%2,%3};"
        : "+f"(d[0]), "+f"(d[1]), "+f"(d[2]), "+f"(d[3])
        : "r"(a[0]), "r"(a[1]), "r"(a[2]), "r"(a[3]), "r"(b[0]), "r"(b[1]));
}

__device__ __forceinline__ void cp16(void* smem_dst, const void* gsrc, int src_bytes) {
    uint32_t d = (uint32_t)__cvta_generic_to_shared(smem_dst);
    asm volatile("cp.async.cg.shared.global [%0], [%1], 16, %2;"
                 :: "r"(d), "l"(gsrc), "r"(src_bytes));
}
#define CP_COMMIT asm volatile("cp.async.commit_group;")
#define CP_WAIT(n) asm volatile("cp.async.wait_group %0;" :: "n"(n))

// ---------------- basis ------------------------------------------------------
__global__ void basis_kernel(const float* __restrict__ nodes,
                             const float* __restrict__ modes,
                             const float* __restrict__ latent,
                             float* __restrict__ cosv, float* __restrict__ sinv) {
    int idx = blockIdx.x * blockDim.x + threadIdx.x;
    if (idx >= BB * NN) return;
    float il0 = 0.5f + 1.5f / (1.f + expf(-latent[0]));
    float il1 = 0.5f + 1.5f / (1.f + expf(-latent[1]));
    float il2 = 0.5f + 1.5f / (1.f + expf(-latent[2]));
    float n0 = nodes[idx * 3 + 0];
    float n1 = nodes[idx * 3 + 1];
    float n2 = nodes[idx * 3 + 2];
    #pragma unroll
    for (int k = 0; k < NM; k++) {
        float t = n0 * modes[k * 3 + 0] * il0
                + n1 * modes[k * 3 + 1] * il1
                + n2 * modes[k * 3 + 2] * il2;
        float s, c;
        sincosf(t, &s, &c);
        cosv[idx * NM + k] = to_tf32(c);
        sinv[idx * NM + k] = to_tf32(s);
    }
}

// ---------------- fc0 --------------------------------------------------------
__global__ void fc0_kernel(const float* __restrict__ x, const float* __restrict__ w,
                           const float* __restrict__ bias, float* __restrict__ h) {
    int idx = blockIdx.x * blockDim.x + threadIdx.x;
    if (idx >= BB * NN * CC) return;
    int c = idx & 127;
    int node = idx >> 7;
    float v = bias[c] + x[node * 3 + 0] * w[c * 3 + 0]
                      + x[node * 3 + 1] * w[c * 3 + 1]
                      + x[node * 3 + 2] * w[c * 3 + 2];
    h[idx] = to_tf32(v);
}

// ---------------- CSR build --------------------------------------------------
__global__ void hist_kernel(const int* __restrict__ edges, int* __restrict__ count) {
    int idx = blockIdx.x * blockDim.x + threadIdx.x;
    if (idx >= BB * EE) return;
    int b = idx / EE;
    int tgt = edges[idx * 2 + 0];
    atomicAdd(&count[b * NN + tgt], 1);
}

__global__ void scan_kernel(const int* __restrict__ count, int* __restrict__ offsets) {
    int b = blockIdx.x;
    int t = threadIdx.x;              // 1024
    __shared__ int sums[1024];
    const int CH = 20;
    int base = t * CH;
    int s = 0;
    for (int i = 0; i < CH; i++) {
        int n = base + i;
        if (n < NN) s += count[b * NN + n];
    }
    sums[t] = s;
    __syncthreads();
    for (int off = 1; off < 1024; off <<= 1) {
        int v = (t >= off) ? sums[t - off] : 0;
        __syncthreads();
        sums[t] += v;
        __syncthreads();
    }
    int run = (t == 0) ? 0 : sums[t - 1];
    for (int i = 0; i < CH; i++) {
        int n = base + i;
        if (n < NN) {
            offsets[b * (NN + 1) + n] = run;
            run += count[b * NN + n];
        }
    }
    if (t == 1023) offsets[b * (NN + 1) + NN] = sums[1023];
}

__global__ void fill_kernel(const int* __restrict__ edges, const float* __restrict__ egw,
                            const int* __restrict__ offsets, int* __restrict__ cursor,
                            int* __restrict__ esrc, float* __restrict__ ew3) {
    int idx = blockIdx.x * blockDim.x + threadIdx.x;
    if (idx >= BB * EE) return;
    int b = idx / EE;
    int tgt = edges[idx * 2 + 0];
    int src = edges[idx * 2 + 1];
    int pos = offsets[b * (NN + 1) + tgt] + atomicAdd(&cursor[b * NN + tgt], 1);
    int gp = b * EE + pos;
    esrc[gp] = src;
    ew3[(size_t)gp * 3 + 0] = egw[(size_t)idx * 3 + 0];
    ew3[(size_t)gp * 3 + 1] = egw[(size_t)idx * 3 + 1];
    ew3[(size_t)gp * 3 + 2] = egw[(size_t)idx * 3 + 2];
}

// ---------------- gradient gather (batched) ----------------------------------
#define NPB 8
#define ECH 128
__global__ void __launch_bounds__(128)
gather_kernel(const float* __restrict__ h,
              const int* __restrict__ offsets,
              const int* __restrict__ esrc,
              const float* __restrict__ ew3,
              float* __restrict__ g) {
    int b = blockIdx.y;
    int c = threadIdx.x;   // 128
    int n0 = blockIdx.x * NPB;
    __shared__ int s_off[NPB + 1];
    __shared__ int s_src[ECH];
    __shared__ float s_w[ECH * 3];
    if (c <= NPB) s_off[c] = offsets[b * (NN + 1) + n0 + c];
    __syncthreads();
    int e0 = s_off[0], e1 = s_off[NPB];
    const float* hb = h + (size_t)(b * NN) * CC;
    float ht[NPB];
    float acc[NPB][3];
    #pragma unroll
    for (int i = 0; i < NPB; i++) {
        ht[i] = hb[(n0 + i) * CC + c];
        acc[i][0] = acc[i][1] = acc[i][2] = 0.f;
    }
    size_t ebase = (size_t)b * EE;
    for (int cbase = e0; cbase < e1; cbase += ECH) {
        int cnt = min(ECH, e1 - cbase);
        __syncthreads();
        if (c < cnt) s_src[c] = esrc[ebase + cbase + c];
        for (int l = c; l < cnt * 3; l += 128)
            s_w[l] = ew3[(ebase + cbase) * 3 + l];
        __syncthreads();
        #pragma unroll
        for (int i = 0; i < NPB; i++) {
            int lo = max(s_off[i] - cbase, 0);
            int hi = min(s_off[i + 1] - cbase, cnt);
            for (int j = lo; j < hi; j++) {
                float hs = hb[s_src[j] * CC + c];
                float d = hs - ht[i];
                acc[i][0] += s_w[j * 3 + 0] * d;
                acc[i][1] += s_w[j * 3 + 1] * d;
                acc[i][2] += s_w[j * 3 + 2] * d;
            }
        }
    }
    #pragma unroll
    for (int i = 0; i < NPB; i++) {
        size_t gb_ = (size_t)(b * NN + n0 + i) * 384 + c * 3;
        g[gb_ + 0] = to_tf32(acc[i][0]);
        g[gb_ + 1] = to_tf32(acc[i][1]);
        g[gb_ + 2] = to_tf32(acc[i][2]);
    }
}

// ---------------- forward spectral transform (batched) -----------------------
#define FNCH 200
__global__ void __launch_bounds__(256)
forward_mma(const float* __restrict__ h,
            const float* __restrict__ cosv,
            const float* __restrict__ sinv,
            const float* __restrict__ nw,
            float* __restrict__ xcs) {
    __shared__ float Ah[80][20];
    __shared__ float Hs[2][16][136];
    int b = blockIdx.y;
    int n0 = blockIdx.x * FNCH;
    int tid = threadIdx.x;
    int warp = tid >> 5, lane = tid & 31;
    int grp = lane >> 2, tig = lane & 3;

    const float* hb = h + (size_t)(b * NN) * CC;
    const float* cb = cosv + (size_t)(b * NN) * NM;
    const float* sbv = sinv + (size_t)(b * NN) * NM;
    const float* wv = nw + (size_t)b * NN;

    float acc[5][2][4];
    #pragma unroll
    for (int m = 0; m < 5; m++)
        #pragma unroll
        for (int f = 0; f < 2; f++)
            #pragma unroll
            for (int q = 0; q < 4; q++) acc[m][f][q] = 0.f;

    auto issue_h = [&](int kt, int buf) {
        int base_node = n0 + kt * 16;
        #pragma unroll
        for (int r = 0; r < 2; r++) {
            int gi = tid + r * 256;
            int row = gi >> 5;
            int c4 = (gi & 31) * 4;
            cp16(&Hs[buf][row][c4], hb + (size_t)(base_node + row) * CC + c4, 16);
        }
    };

    issue_h(0, 0); CP_COMMIT;

    const int CHUNKS = (FNCH + 15) / 16;
    for (int kt = 0; kt < CHUNKS; kt++) {
        int cur = kt & 1;
        int base_node = n0 + kt * 16;
        int valid = min(16, FNCH - kt * 16);
        #pragma unroll
        for (int i = 0; i < 5; i++) {
            int idx = tid + i * 256;
            int j = idx / 80;
            int r = idx - j * 80;
            float v = 0.f;
            if (j < valid) {
                int node = base_node + j;
                float w = wv[node];
                if (r < 32)       v = w * cb[(size_t)node * NM + r];
                else if (r < 64)  v = w * sbv[(size_t)node * NM + (r - 32)];
                else if (r == 64) v = w;
            }
            Ah[r][j] = to_tf32(v);
        }
        if (kt < CHUNKS - 1) { issue_h(kt + 1, cur ^ 1); CP_COMMIT; CP_WAIT(1); }
        else                 { CP_WAIT(0); }
        __syncthreads();

        #pragma unroll
        for (int k8 = 0; k8 < 2; k8++) {
            int k0 = k8 * 8;
            uint32_t bfr[2][2];
            #pragma unroll
            for (int f = 0; f < 2; f++) {
                int ncol = warp * 16 + f * 8 + grp;
                bfr[f][0] = __float_as_uint(Hs[cur][k0 + tig][ncol]);
                bfr[f][1] = __float_as_uint(Hs[cur][k0 + tig + 4][ncol]);
            }
            uint32_t afr[5][4];
            #pragma unroll
            for (int m = 0; m < 5; m++) {
                int r0 = m * 16 + grp;
                afr[m][0] = __float_as_uint(Ah[r0][k0 + tig]);
                afr[m][1] = __float_as_uint(Ah[r0 + 8][k0 + tig]);
                afr[m][2] = __float_as_uint(Ah[r0][k0 + tig + 4]);
                afr[m][3] = __float_as_uint(Ah[r0 + 8][k0 + tig + 4]);
            }
            #pragma unroll
            for (int m = 0; m < 5; m++)
                #pragma unroll
                for (int f = 0; f < 2; f++)
                    mma_tf32(acc[m][f], afr[m], bfr[f]);
        }
        __syncthreads();
    }

    float* xb = xcs + (size_t)(b * 65) * CC;
    #pragma unroll
    for (int m = 0; m < 5; m++) {
        #pragma unroll
        for (int f = 0; f < 2; f++) {
            #pragma unroll
            for (int half = 0; half < 2; half++) {
                int row = m * 16 + grp + half * 8;
                if (row < 65) {
                    int col = warp * 16 + f * 8 + tig * 2;
                    atomicAdd(&xb[(size_t)row * CC + col],     acc[m][f][half * 2 + 0]);
                    atomicAdd(&xb[(size_t)row * CC + col + 1], acc[m][f][half * 2 + 1]);
                }
            }
        }
    }
}

// ---------------- generic tiled transpose ------------------------------------
__global__ void transpose_kernel(const float* __restrict__ src, float* __restrict__ dst,
                                 int R, int C, int do_round) {
    __shared__ float tile[32][33];
    int c0 = blockIdx.x * 32;
    int r0 = blockIdx.y * 32;
    int tx = threadIdx.x, ty = threadIdx.y;
    #pragma unroll
    for (int i = 0; i < 4; i++) {
        int r = r0 + ty + i * 8;
        int c = c0 + tx;
        if (r < R && c < C) tile[ty + i * 8][tx] = src[r * C + c];
    }
    __syncthreads();
    #pragma unroll
    for (int i = 0; i < 4; i++) {
        int c = c0 + ty + i * 8;
        int r = r0 + tx;
        if (r < R && c < C) {
            float v = tile[tx][ty + i * 8];
            dst[c * R + r] = do_round ? to_tf32(v) : v;
        }
    }
}

// ---------------- mode mixing — 4 batches per block (weight reuse) -----------
__global__ void __launch_bounds__(512)
modemix_kernel(const float* __restrict__ xcs,
               const float* __restrict__ wtc,
               const float* __restrict__ wts,
               const float* __restrict__ sw0_l,
               float* __restrict__ specW, float* __restrict__ f0) {
    int k = blockIdx.x;      // 0..32; 32 => f0
    int tid = threadIdx.x;   // 512
    int b = tid >> 7;
    int o = tid & 127;
    __shared__ float xc_s[4][CC], xs_s[4][CC];
    if (k < 32) {
        xc_s[b][o] = xcs[(b * 65 + k) * CC + o];
        xs_s[b][o] = xcs[(b * 65 + 32 + k) * CC + o];
        __syncthreads();
        float fc = 0.f, fs = 0.f;
        #pragma unroll 8
        for (int c = 0; c < CC; c++) {
            float wc = wtc[(k * CC + c) * CC + o];
            float ws = wts[(k * CC + c) * CC + o];
            float a = xc_s[b][c], s2 = xs_s[b][c];
            fc += a * wc - s2 * ws;
            fs += s2 * wc + a * ws;
        }
        specW[(b * 64 + k) * CC + o]      = to_tf32( 2.f * fc);
        specW[(b * 64 + 32 + k) * CC + o] = to_tf32(-2.f * fs);
    } else {
        xc_s[b][o] = xcs[(b * 65 + 64) * CC + o];
        __syncthreads();
        float f = 0.f;
        #pragma unroll 8
        for (int c = 0; c < CC; c++) f += xc_s[b][c] * sw0_l[c * CC + o];
        f0[b * CC + o] = f;
    }
}

// ---------------- fused combine GEMM — 3-stage ring, occ 4 -------------------
#define CSTAGES 3
#define A_EL (64 * 36)
#define W_EL (16 * 136)
#define CSMEM_BYTES ((CSTAGES * (A_EL + W_EL) + 128) * 4)
__global__ void __launch_bounds__(128, 4)
combine_mma(const float* __restrict__ h, const float* __restrict__ g,
            const float* __restrict__ cosv, const float* __restrict__ sinv,
            const float* __restrict__ wcat, const float* __restrict__ specW,
            const float* __restrict__ f0, const float* __restrict__ wb,
            const float* __restrict__ gb, float* __restrict__ hout,
            int gelu_flag) {
    extern __shared__ float dsm[];
    float (*As)[64][36] = (float(*)[64][36])dsm;
    float (*Ws)[16][136] = (float(*)[16][136])(dsm + CSTAGES * A_EL);
    float* bias_s = dsm + CSTAGES * (A_EL + W_EL);

    int b = blockIdx.y;
    int n0 = blockIdx.x * 64;
    int tid = threadIdx.x;          // 128
    int warp = tid >> 5, lane = tid & 31;
    int grp = lane >> 2, tig = lane & 3;
    int wm = (warp >> 1) * 32;
    int wn = (warp & 1) * 64;

    bias_s[tid] = wb[tid] + gb[tid] + f0[b * CC + tid];

    float acc[2][8][4];
    #pragma unroll
    for (int i = 0; i < 2; i++)
        #pragma unroll
        for (int j = 0; j < 8; j++)
            #pragma unroll
            for (int q = 0; q < 4; q++) acc[i][j][q] = 0.f;

    const float* hb  = h + (size_t)(b * NN) * 128;
    const float* gbp = g + (size_t)(b * NN) * 384;
    const float* cb  = cosv + (size_t)(b * NN) * 32;
    const float* sb2 = sinv + (size_t)(b * NN) * 32;
    const float* spb = specW + (size_t)(b * 64) * 128;

    auto issue_tile = [&](int kt, int buf) {
        int kbase = kt * 16;
        #pragma unroll
        for (int r = 0; r < 2; r++) {
            int gi = tid + r * 128;
            int m = gi >> 2;
            int k4 = (gi & 3) * 4;
            int n = n0 + m;
            int nc = (n < NN) ? n : 0;
            int k = kbase + k4;
            const float* src;
            if (k < 128)      src = hb + (size_t)nc * 128 + k;
            else if (k < 512) src = gbp + (size_t)nc * 384 + (k - 128);
            else if (k < 544) src = cb + (size_t)nc * 32 + (k - 512);
            else              src = sb2 + (size_t)nc * 32 + (k - 544);
            cp16(&As[buf][m][k4], src, (n < NN) ? 16 : 0);
        }
        #pragma unroll
        for (int r = 0; r < 4; r++) {
            int gi = tid + r * 128;
            int kk = gi >> 5;
            int o4 = (gi & 31) * 4;
            int k = kbase + kk;
            const float* src = (k < 512) ? wcat + (size_t)k * 128 + o4
                                         : spb + (size_t)(k - 512) * 128 + o4;
            cp16(&Ws[buf][kk][o4], src, 16);
        }
    };

    issue_tile(0, 0); CP_COMMIT;
    issue_tile(1, 1); CP_COMMIT;

    for (int kt = 0; kt < 36; kt++) {
        int cur = kt % 3;
        if (kt < 35) CP_WAIT(1);
        else CP_WAIT(0);
        __syncthreads();
        if (kt < 34) {
            issue_tile(kt + 2, (kt + 2) % 3);
            CP_COMMIT;
        }
        #pragma unroll
        for (int k8 = 0; k8 < 2; k8++) {
            int k0 = k8 * 8;
            uint32_t afr[2][4];
            #pragma unroll
            for (int i = 0; i < 2; i++) {
                int r0 = wm + i * 16 + grp;
                afr[i][0] = __float_as_uint(As[cur][r0][k0 + tig]);
                afr[i][1] = __float_as_uint(As[cur][r0 + 8][k0 + tig]);
                afr[i][2] = __float_as_uint(As[cur][r0][k0 + tig + 4]);
                afr[i][3] = __float_as_uint(As[cur][r0 + 8][k0 + tig + 4]);
            }
            uint32_t bfr[8][2];
            #pragma unroll
            for (int j = 0; j < 8; j++) {
                int o = wn + j * 8 + grp;
                bfr[j][0] = __float_as_uint(Ws[cur][k0 + tig][o]);
                bfr[j][1] = __float_as_uint(Ws[cur][k0 + tig + 4][o]);
            }
            #pragma unroll
            for (int i = 0; i < 2; i++)
                #pragma unroll
                for (int j = 0; j < 8; j++)
                    mma_tf32(acc[i][j], afr[i], bfr[j]);
        }
        // no trailing barrier: next iteration's top-of-loop __syncthreads orders
        // these LDS reads before buffer (kt+2)%3's overwrite (issued after it).
    }

    // epilogue
    #pragma unroll
    for (int i = 0; i < 2; i++) {
        int row0 = wm + i * 16 + grp;
        #pragma unroll
        for (int j = 0; j < 8; j++) {
            int col = wn + j * 8 + tig * 2;
            #pragma unroll
            for (int half = 0; half < 2; half++) {
                int n = n0 + row0 + half * 8;
                if (n < NN) {
                    float v0 = acc[i][j][half * 2 + 0] + bias_s[col];
                    float v1 = acc[i][j][half * 2 + 1] + bias_s[col + 1];
                    if (gelu_flag) {
                        v0 = to_tf32(gelu_f(v0));
                        v1 = to_tf32(gelu_f(v1));
                    }
                    hout[(size_t)(b * NN + n) * CC + col]     = v0;
                    hout[(size_t)(b * NN + n) * CC + col + 1] = v1;
                }
            }
        }
    }
}

// ---------------- final fused MLP GEMM ---------------------------------------
__global__ void __launch_bounds__(256, 2)
final_gemm(const float* __restrict__ h, const float* __restrict__ fc1wt,
           const float* __restrict__ fc1_b, const float* __restrict__ fc2_w,
           const float* __restrict__ fc2_b, float* __restrict__ out) {
    int m0 = blockIdx.x * 128;
    int tid = threadIdx.x;
    int tx = tid & 15, ty = tid >> 4;
    __shared__ float As[128][17];
    __shared__ float Ws[16][128];
    float acc[8][8];
    #pragma unroll
    for (int i = 0; i < 8; i++)
        #pragma unroll
        for (int j = 0; j < 8; j++) acc[i][j] = 0.f;

    for (int kt = 0; kt < 8; kt++) {
        int kbase = kt * 16;
        #pragma unroll
        for (int r = 0; r < 8; r++) {
            int l = tid + r * 256;
            int nl = l >> 4, kk = l & 15;
            As[nl][kk] = h[(m0 + nl) * CC + kbase + kk];
        }
        #pragma unroll
        for (int r = 0; r < 8; r++) {
            int l = tid + r * 256;
            int kk = l >> 7, o = l & 127;
            Ws[kk][o] = fc1wt[(kbase + kk) * CC + o];
        }
        __syncthreads();
        #pragma unroll
        for (int kk = 0; kk < 16; kk++) {
            float a[8];
            #pragma unroll
            for (int i = 0; i < 8; i++) a[i] = As[ty + 16 * i][kk];
            float4 w0 = *(const float4*)&Ws[kk][tx * 4];
            float4 w1 = *(const float4*)&Ws[kk][64 + tx * 4];
            float w[8] = {w0.x, w0.y, w0.z, w0.w, w1.x, w1.y, w1.z, w1.w};
            #pragma unroll
            for (int i = 0; i < 8; i++)
                #pragma unroll
                for (int j = 0; j < 8; j++) acc[i][j] += a[i] * w[j];
        }
        __syncthreads();
    }
    float part[8];
    #pragma unroll
    for (int i = 0; i < 8; i++) {
        float p = 0.f;
        #pragma unroll
        for (int j = 0; j < 8; j++) {
            int o = (j < 4) ? (tx * 4 + j) : (64 + tx * 4 + (j - 4));
            float v = acc[i][j] + fc1_b[o];
            v = gelu_f(v);
            p += v * fc2_w[o];
        }
        part[i] = p;
    }
    __syncthreads();
    #pragma unroll
    for (int i = 0; i < 8; i++) As[ty + 16 * i][tx] = part[i];
    __syncthreads();
    if (tid < 128) {
        float s = 0.f;
        #pragma unroll
        for (int t = 0; t < 16; t++) s += As[tid][t];
        out[m0 + tid] = s + fc2_b[0];
    }
}

// ---------------- launcher ----------------------------------------------------
extern "C" void kernel_launch(void* const* d_in, const int* in_sizes, int n_in,
                              void* d_out, int out_size) {
    const float* x      = (const float*)d_in[0];
    const float* nodes  = (const float*)d_in[2];
    const float* nw     = (const float*)d_in[3];
    const int*   edges  = (const int*)  d_in[4];
    const float* egw    = (const float*)d_in[5];
    const float* modes  = (const float*)d_in[6];
    const float* latent = (const float*)d_in[7];
    const float* fc0_w  = (const float*)d_in[8];
    const float* fc0_b  = (const float*)d_in[9];
    const float* swc    = (const float*)d_in[10];
    const float* sws    = (const float*)d_in[11];
    const float* sw0    = (const float*)d_in[12];
    const float* ww     = (const float*)d_in[13];
    const float* wb     = (const float*)d_in[14];
    const float* gw     = (const float*)d_in[15];
    const float* gb     = (const float*)d_in[16];
    const float* fc1_w  = (const float*)d_in[17];
    const float* fc1_b  = (const float*)d_in[18];
    const float* fc2_w  = (const float*)d_in[19];
    const float* fc2_b  = (const float*)d_in[20];
    float* out = (float*)d_out;

    float *hA, *hB, *g, *cosv, *sinv, *xcs3, *specW, *f0, *wcat3, *wtc3, *wts3, *fc1wt, *ew3;
    int *count, *cursor, *offsets, *esrc;
    cudaGetSymbolAddress((void**)&hA,      d_hA);
    cudaGetSymbolAddress((void**)&hB,      d_hB);
    cudaGetSymbolAddress((void**)&g,       d_g);
    cudaGetSymbolAddress((void**)&cosv,    d_cosv);
    cudaGetSymbolAddress((void**)&sinv,    d_sinv);
    cudaGetSymbolAddress((void**)&xcs3,    d_xcs3);
    cudaGetSymbolAddress((void**)&specW,   d_specW);
    cudaGetSymbolAddress((void**)&f0,      d_f0);
    cudaGetSymbolAddress((void**)&wcat3,   d_wcat3);
    cudaGetSymbolAddress((void**)&wtc3,    d_wtc3);
    cudaGetSymbolAddress((void**)&wts3,    d_wts3);
    cudaGetSymbolAddress((void**)&fc1wt,   d_fc1wt);
    cudaGetSymbolAddress((void**)&count,   d_count);
    cudaGetSymbolAddress((void**)&cursor,  d_cursor);
    cudaGetSymbolAddress((void**)&offsets, d_offsets);
    cudaGetSymbolAddress((void**)&esrc,    d_esrc);
    cudaGetSymbolAddress((void**)&ew3,     d_ew3);

    static cudaStream_t s1 = nullptr, s2 = nullptr;
    static cudaEvent_t  ev[14];
    if (s1 == nullptr) {
        cudaStreamCreateWithFlags(&s1, cudaStreamNonBlocking);
        cudaStreamCreateWithFlags(&s2, cudaStreamNonBlocking);
        for (int i = 0; i < 14; i++)
            cudaEventCreateWithFlags(&ev[i], cudaEventDisableTiming);
    }
    enum { E_ROOT = 0, E_FC0, E_BASIS, E_G0, E_G1, E_G2, E_C0, E_C1,
           E_WT0, E_WT1, E_WT2, E_XCS };

    static bool smem_set = false;
    if (!smem_set) {
        cudaFuncSetAttribute(combine_mma, cudaFuncAttributeMaxDynamicSharedMemorySize,
                             CSMEM_BYTES);
        smem_set = true;
    }

    dim3 t32x8(32, 8);
    const size_t XCS_SZ = (size_t)BB * 65 * CC;

    // fork
    cudaEventRecord(ev[E_ROOT], 0);
    cudaStreamWaitEvent(s1, ev[E_ROOT], 0);
    cudaStreamWaitEvent(s2, ev[E_ROOT], 0);

    fc0_kernel<<<(BB * NN * CC + 255) / 256, 256>>>(x, fc0_w, fc0_b, hA);
    cudaEventRecord(ev[E_FC0], 0);
    basis_kernel<<<(BB * NN + 127) / 128, 128, 0, s1>>>(nodes, modes, latent,
                                                        cosv, sinv);
    cudaEventRecord(ev[E_BASIS], s1);
    cudaMemsetAsync(count, 0, BB * NN * sizeof(int), s1);
    cudaMemsetAsync(cursor, 0, BB * NN * sizeof(int), s1);

    // S2: xcs memsets (all 3 layers) + weight transposes
    cudaMemsetAsync(xcs3, 0, 3 * XCS_SZ * sizeof(float), s2);
    cudaEventRecord(ev[E_XCS], s2);
    transpose_kernel<<<dim3(4, 4), t32x8, 0, s2>>>(fc1_w, fc1wt, CC, CC, 0);
    for (int l = 0; l < 3; l++) {
        transpose_kernel<<<dim3(1, 512), t32x8, 0, s2>>>(
            swc + (size_t)l * CC * CC * NM, wtc3 + (size_t)l * NM * CC * CC, CC * CC, NM, 0);
        transpose_kernel<<<dim3(1, 512), t32x8, 0, s2>>>(
            sws + (size_t)l * CC * CC * NM, wts3 + (size_t)l * NM * CC * CC, CC * CC, NM, 0);
        transpose_kernel<<<dim3(4, 4), t32x8, 0, s2>>>(
            ww + (size_t)l * CC * CC, wcat3 + (size_t)l * 512 * CC, CC, CC, 1);
        transpose_kernel<<<dim3(12, 4), t32x8, 0, s2>>>(
            gw + (size_t)l * CC * 384, wcat3 + (size_t)l * 512 * CC + 128 * CC, CC, 384, 1);
        cudaEventRecord(ev[E_WT0 + l], s2);
    }

    // S1: CSR + gather-l0
    hist_kernel<<<(BB * EE + 255) / 256, 256, 0, s1>>>(edges, count);
    scan_kernel<<<BB, 1024, 0, s1>>>(count, offsets);
    fill_kernel<<<(BB * EE + 255) / 256, 256, 0, s1>>>(edges, egw, offsets, cursor,
                                                       esrc, ew3);
    cudaStreamWaitEvent(s1, ev[E_FC0], 0);
    gather_kernel<<<dim3(NN / NPB, BB), 128, 0, s1>>>(hA, offsets, esrc, ew3, g);
    cudaEventRecord(ev[E_G0], s1);

    // S0 spine
    float* hin = hA;
    float* hout = hB;
    cudaStreamWaitEvent(0, ev[E_BASIS], 0);
    cudaStreamWaitEvent(0, ev[E_XCS], 0);
    for (int l = 0; l < 3; l++) {
        float* xcs = xcs3 + (size_t)l * XCS_SZ;
        forward_mma<<<dim3(NN / FNCH, BB), 256>>>(hin, cosv, sinv, nw, xcs);
        cudaStreamWaitEvent(0, ev[E_WT0 + l], 0);
        modemix_kernel<<<33, 512>>>(
            xcs, wtc3 + (size_t)l * NM * CC * CC, wts3 + (size_t)l * NM * CC * CC,
            sw0 + (size_t)l * CC * CC, specW, f0);
        cudaStreamWaitEvent(0, ev[E_G0 + l], 0);
        combine_mma<<<dim3((NN + 63) / 64, BB), 128, CSMEM_BYTES>>>(
            hin, g, cosv, sinv, wcat3 + (size_t)l * 512 * CC, specW, f0,
            wb + l * CC, gb + l * CC, hout, (l < 2) ? 1 : 0);
        if (l < 2) {
            cudaEventRecord(ev[E_C0 + l], 0);
            cudaStreamWaitEvent(s1, ev[E_C0 + l], 0);
            gather_kernel<<<dim3(NN / NPB, BB), 128, 0, s1>>>(hout, offsets, esrc, ew3, g);
            cudaEventRecord(ev[E_G1 + l], s1);
        }
        float* t = hin; hin = hout; hout = t;
    }
    final_gemm<<<(BB * NN) / 128, 256>>>(hin, fc1wt, fc1_b, fc2_w, fc2_b, out);
}